// round 6
// baseline (speedup 1.0000x reference)
#include <cuda_runtime.h>
#include <cstdint>

#define BB    32
#define NN    1024
#define ND    14
#define HID   64
#define HEADD 128
#define MAXN  64
#define ROWS  (BB*NN)          // 32768
#define RPB   64               // rows per block in agg kernels
#define NBLK  (ROWS/RPB)       // 512
#define PAD   66               // padded h-row stride (floats)

typedef unsigned long long ull;

#define FMA2(d, a, b, c) \
    asm("fma.rn.f32x2 %0, %1, %2, %3;" : "=l"(d) : "l"(a), "l"(b), "l"(c))
#define ADD2(d, a, b) \
    asm("add.rn.f32x2 %0, %1, %2;" : "=l"(d) : "l"(a), "l"(b))
#define PACK2(d, lo, hi) \
    asm("mov.b64 %0, {%1, %2};" : "=l"(d) : "f"(lo), "f"(hi))
#define DUP2(d, s) \
    asm("mov.b64 %0, {%1, %1};" : "=l"(d) : "f"(s))
#define UNPACK2(lo, hi, s) \
    asm("mov.b64 {%0, %1}, %2;" : "=f"(lo), "=f"(hi) : "l"(s))

// ---------------- scratch (device globals; no allocations) ----------------
__device__ unsigned short g_nbr[ROWS * MAXN];   // ELL neighbor lists (cols < 1024)
__device__ int   g_cnt[ROWS];
__device__ float g_dinv[ROWS];
__device__ float g_bufA[ROWS * HID];
__device__ float g_bufB[ROWS * HID];
__device__ float g_pool[NBLK * HID];            // per-block pool partials

// ---------------------------------------------------------------------------
// K1: one warp per adjacency row. Load 8 float4 up-front (MLP=8), warp-scan,
// store uint16 ELL list + dinv. 128MB read once -> HBM-bound (~16-20us).
// ---------------------------------------------------------------------------
__global__ void k_adj(const float4* __restrict__ adj4) {
    int gtid = blockIdx.x * blockDim.x + threadIdx.x;
    int row  = gtid >> 5;
    int lane = gtid & 31;
    if (row >= ROWS) return;

    const float4* rp = adj4 + (size_t)row * (NN / 4);
    float4 v[8];
    #pragma unroll
    for (int k = 0; k < 8; ++k) v[k] = rp[k * 32 + lane];

    int base = row * MAXN;
    int cnt = 0;
    #pragma unroll
    for (int k = 0; k < 8; ++k) {
        int col0 = (k * 32 + lane) * 4;
        int m = (v[k].x != 0.f ? 1 : 0) | (v[k].y != 0.f ? 2 : 0)
              | (v[k].z != 0.f ? 4 : 0) | (v[k].w != 0.f ? 8 : 0);
        int c = __popc(m);
        int x = c;
        #pragma unroll
        for (int d = 1; d < 32; d <<= 1) {
            int y = __shfl_up_sync(0xffffffffu, x, d);
            if (lane >= d) x += y;
        }
        int w   = cnt + x - c;
        int tot = __shfl_sync(0xffffffffu, x, 31);
        if (m & 1) { if (w < MAXN) g_nbr[base + w] = (unsigned short)col0;       w++; }
        if (m & 2) { if (w < MAXN) g_nbr[base + w] = (unsigned short)(col0 + 1); w++; }
        if (m & 4) { if (w < MAXN) g_nbr[base + w] = (unsigned short)(col0 + 2); w++; }
        if (m & 8) { if (w < MAXN) g_nbr[base + w] = (unsigned short)(col0 + 3); w++; }
        cnt += tot;
    }
    if (lane == 0) {
        g_cnt[row]  = cnt;
        g_dinv[row] = rsqrtf((float)(cnt > 0 ? cnt : 1));
    }
}

// ---------------------------------------------------------------------------
// K2: z0[row] = dinv[row] * (x[row] @ W1). 64 rows / 256-thread block.
// ---------------------------------------------------------------------------
__global__ void __launch_bounds__(256) k_lin0(const float* __restrict__ x,
                                              const float* __restrict__ W1,
                                              float* __restrict__ out) {
    int tid = threadIdx.x;
    int g   = tid >> 6;
    int t   = tid & 63;
    int R0  = blockIdx.x * 64;

    __shared__ float sx[64 * ND];
    __shared__ float sdinv[64];

    float wreg[ND];
    #pragma unroll
    for (int c = 0; c < ND; ++c) wreg[c] = W1[c * HID + t];

    for (int i = tid; i < 64 * ND; i += 256) sx[i] = x[(size_t)R0 * ND + i];
    if (tid < 64) sdinv[tid] = g_dinv[R0 + tid];
    __syncthreads();

    #pragma unroll 4
    for (int rr = 0; rr < 16; ++rr) {
        int r = g * 16 + rr;
        const float* xr = sx + r * ND;
        float a = 0.f;
        #pragma unroll
        for (int c = 0; c < ND; ++c) a = fmaf(xr[c], wreg[c], a);
        out[(size_t)(R0 + r) * HID + t] = a * sdinv[r];
    }
}

// ---------------------------------------------------------------------------
// K3: fused aggregation layer, 64 rows / 256-thread block.
//  Phase 1: warp w handles rows w*8..w*8+7 interleaved; lane = channel pair;
//           gather via LDG.64, packed add.rn.f32x2 accumulators. relu ->
//           padded smem (HAS_MV) or pool partial (!HAS_MV).
//  Phase 2 (HAS_MV): 64x64x64 micro-GEMM, thread tile 2 rows x 8 cols,
//           packed fma.rn.f32x2: per c = 2 LDS.128(W) + 2 LDS(h) + 2 DUP
//           + 8 FMA2.
// ---------------------------------------------------------------------------
template <int HAS_MV>
__global__ void __launch_bounds__(256) k_agg(const float* __restrict__ zin,
                                             const float* __restrict__ bias,
                                             const float* __restrict__ Wnext,
                                             float* __restrict__ out) {
    int tid  = threadIdx.x;
    int w    = tid >> 5;
    int lane = tid & 31;
    int R0   = blockIdx.x * RPB;
    int bbase = (R0 >> 10) << 10;                 // batch * N

    __shared__ unsigned short sidx[RPB * MAXN];   // 8 KB
    __shared__ float sh[HAS_MV ? RPB * PAD : 1];  // 16.9 KB
    __shared__ float sW[HAS_MV ? HID * HID : 1];  // 16 KB
    __shared__ float sdinv[RPB];
    __shared__ int   scnt[RPB];
    __shared__ float2 spart[8][32];

    // ---- stage: ELL lists (int4), W (float4), dinv, cnt ----
    {
        const int4* src = (const int4*)(g_nbr + (size_t)R0 * MAXN);
        int4* dst = (int4*)sidx;
        #pragma unroll
        for (int i = 0; i < RPB * MAXN * 2 / 16 / 256; ++i)   // 2 iters
            dst[tid + i * 256] = src[tid + i * 256];
        if (HAS_MV) {
            const float4* ws = (const float4*)Wnext;
            float4* wd = (float4*)sW;
            #pragma unroll
            for (int i = 0; i < HID * HID / 4 / 256; ++i)     // 4 iters
                wd[tid + i * 256] = ws[tid + i * 256];
        }
        if (tid < RPB) {
            int c = g_cnt[R0 + tid];
            scnt[tid]  = c > MAXN ? MAXN : c;
            sdinv[tid] = g_dinv[R0 + tid];
        }
    }
    __syncthreads();

    // ---- phase 1: 8 rows per warp, interleaved gather, packed adds ----
    {
        const float2 bf = ((const float2*)bias)[lane];
        const ull* zb = (const ull*)zin + (size_t)bbase * (HID / 2) + lane;

        int r0 = w * 8;
        int cn[8];
        const unsigned short* ip[8];
        ull acc[8];
        #pragma unroll
        for (int i = 0; i < 8; ++i) {
            cn[i]  = scnt[r0 + i];
            ip[i]  = sidx + (r0 + i) * MAXN;
            acc[i] = 0ull;
        }
        int cmax = 0;
        #pragma unroll
        for (int i = 0; i < 8; ++i) cmax = max(cmax, cn[i]);

        for (int k = 0; k < cmax; ++k) {
            #pragma unroll
            for (int i = 0; i < 8; ++i) {
                if (k < cn[i]) {
                    ull v = zb[ip[i][k] * (HID / 2)];
                    ADD2(acc[i], acc[i], v);
                }
            }
        }

        float2 pacc = make_float2(0.f, 0.f);
        #pragma unroll
        for (int i = 0; i < 8; ++i) {
            float ax, ay;
            UNPACK2(ax, ay, acc[i]);
            float di = sdinv[r0 + i];
            float hx = fmaxf(fmaf(di, ax, bf.x), 0.f);
            float hy = fmaxf(fmaf(di, ay, bf.y), 0.f);
            if (HAS_MV) {
                *(float2*)(sh + (r0 + i) * PAD + 2 * lane) = make_float2(hx, hy);
            } else {
                pacc.x += hx; pacc.y += hy;
            }
        }

        if (!HAS_MV) {
            spart[w][lane] = pacc;
            __syncthreads();
            if (tid < 32) {
                float2 s = spart[0][tid];
                #pragma unroll
                for (int i = 1; i < 8; ++i) { s.x += spart[i][tid].x; s.y += spart[i][tid].y; }
                *(float2*)(out + blockIdx.x * HID + 2 * tid) = s;
            }
            return;
        }
    }

    __syncthreads();

    // ---- phase 2: 64x64x64 micro-GEMM, 2 rows x 8 cols per thread, FMA2 ----
    {
        int tx = tid & 7;           // cols 8*tx .. 8*tx+7
        int ty = tid >> 3;          // rows 2*ty, 2*ty+1

        ull acc[2][4];
        #pragma unroll
        for (int i = 0; i < 2; ++i)
            #pragma unroll
            for (int j = 0; j < 4; ++j) acc[i][j] = 0ull;

        const float* shb = sh + (2 * ty) * PAD;
        const float* wb  = sW + 8 * tx;
        #pragma unroll 4
        for (int c = 0; c < HID; ++c) {
            ulonglong2 wa = *(const ulonglong2*)(wb + c * HID);
            ulonglong2 wc = *(const ulonglong2*)(wb + c * HID + 4);
            float h0 = shb[c];
            float h1 = shb[PAD + c];
            ull hh0; DUP2(hh0, h0);
            ull hh1; DUP2(hh1, h1);
            FMA2(acc[0][0], hh0, wa.x, acc[0][0]);
            FMA2(acc[0][1], hh0, wa.y, acc[0][1]);
            FMA2(acc[0][2], hh0, wc.x, acc[0][2]);
            FMA2(acc[0][3], hh0, wc.y, acc[0][3]);
            FMA2(acc[1][0], hh1, wa.x, acc[1][0]);
            FMA2(acc[1][1], hh1, wa.y, acc[1][1]);
            FMA2(acc[1][2], hh1, wc.x, acc[1][2]);
            FMA2(acc[1][3], hh1, wc.y, acc[1][3]);
        }

        #pragma unroll
        for (int i = 0; i < 2; ++i) {
            int r = 2 * ty + i;
            float di = sdinv[r];
            float a0, a1, a2, a3, a4, a5, a6, a7;
            UNPACK2(a0, a1, acc[i][0]);
            UNPACK2(a2, a3, acc[i][1]);
            UNPACK2(a4, a5, acc[i][2]);
            UNPACK2(a6, a7, acc[i][3]);
            float4 o0, o1;
            o0.x = di * a0; o0.y = di * a1; o0.z = di * a2; o0.w = di * a3;
            o1.x = di * a4; o1.y = di * a5; o1.z = di * a6; o1.w = di * a7;
            float* op = out + (size_t)(R0 + r) * HID + 8 * tx;
            *(float4*)(op)     = o0;
            *(float4*)(op + 4) = o1;
        }
    }
}

// ---------------------------------------------------------------------------
// K4: per batch: pooled = mean of 16 block partials; relu(pooled@Wf1+bf1)@Wf2+bf2
// ---------------------------------------------------------------------------
__global__ void k_final(const float* __restrict__ pool,
                        const float* __restrict__ Wf1, const float* __restrict__ bf1,
                        const float* __restrict__ Wf2, const float* __restrict__ bf2,
                        float* __restrict__ out) {
    int b   = blockIdx.x;
    int tid = threadIdx.x;           // 128 threads
    __shared__ float pooled[HID];
    __shared__ float hred[HEADD];

    if (tid < HID) {
        float s = 0.f;
        #pragma unroll
        for (int i = 0; i < NN / RPB; ++i)
            s += pool[(b * (NN / RPB) + i) * HID + tid];
        pooled[tid] = s * (1.f / NN);
    }
    __syncthreads();

    float a = bf1[tid];
    #pragma unroll
    for (int c = 0; c < HID; ++c) a = fmaf(pooled[c], Wf1[c * HEADD + tid], a);
    hred[tid] = fmaxf(a, 0.f) * Wf2[tid];
    __syncthreads();

    if (tid < 32) {
        float s = hred[tid] + hred[tid + 32] + hred[tid + 64] + hred[tid + 96];
        #pragma unroll
        for (int d = 16; d; d >>= 1) s += __shfl_down_sync(0xffffffffu, s, d);
        if (tid == 0) out[b] = s + bf2[0];
    }
}

// ---------------------------------------------------------------------------
extern "C" void kernel_launch(void* const* d_in, const int* in_sizes, int n_in,
                              void* d_out, int out_size) {
    const float* x    = (const float*)d_in[0];
    const float* adj  = (const float*)d_in[1];
    const float* W1   = (const float*)d_in[2];
    const float* b1   = (const float*)d_in[3];
    const float* W2   = (const float*)d_in[4];
    const float* b2   = (const float*)d_in[5];
    const float* W3   = (const float*)d_in[6];
    const float* b3   = (const float*)d_in[7];
    const float* Wf1  = (const float*)d_in[8];
    const float* bf1  = (const float*)d_in[9];
    const float* Wf2  = (const float*)d_in[10];
    const float* bf2  = (const float*)d_in[11];
    float* out = (float*)d_out;

    float *bufA, *bufB, *pool;
    cudaGetSymbolAddress((void**)&bufA, g_bufA);
    cudaGetSymbolAddress((void**)&bufB, g_bufB);
    cudaGetSymbolAddress((void**)&pool, g_pool);

    k_adj<<<ROWS * 32 / 256, 256>>>((const float4*)adj);       // ELL + dinv
    k_lin0<<<ROWS / 64, 256>>>(x, W1, bufA);                   // z0
    k_agg<1><<<NBLK, 256>>>(bufA, b1, W2, bufB);               // layer1 -> z1
    k_agg<1><<<NBLK, 256>>>(bufB, b2, W3, bufA);               // layer2 -> z2
    k_agg<0><<<NBLK, 256>>>(bufA, b3, nullptr, pool);          // layer3 -> pool partials
    k_final<<<BB, HEADD>>>(pool, Wf1, bf1, Wf2, bf2, out);     // head
}

// round 7
// speedup vs baseline: 1.1368x; 1.1368x over previous
#include <cuda_runtime.h>
#include <cstdint>

#define BB    32
#define NN    1024
#define ND    14
#define HID   64
#define HEADD 128
#define MAXN  64
#define ROWS  (BB*NN)          // 32768
#define GRPB  32               // rows per block (gather + mv kernels)
#define NGB   (ROWS/GRPB)      // 1024
#define MVPAD 65               // padded h stride in k_mv smem

typedef unsigned long long ull;

#define FMA2(d, a, b, c) \
    asm("fma.rn.f32x2 %0, %1, %2, %3;" : "=l"(d) : "l"(a), "l"(b), "l"(c))
#define ADD2(d, a, b) \
    asm("add.rn.f32x2 %0, %1, %2;" : "=l"(d) : "l"(a), "l"(b))
#define DUP2(d, s) \
    asm("mov.b64 %0, {%1, %1};" : "=l"(d) : "f"(s))
#define UNPACK2(lo, hi, s) \
    asm("mov.b64 {%0, %1}, %2;" : "=f"(lo), "=f"(hi) : "l"(s))

// ---------------- scratch (device globals; no allocations) ----------------
__device__ unsigned short g_nbr[ROWS * MAXN];   // ELL neighbor lists
__device__ int   g_cnt[ROWS];
__device__ float g_dinv[ROWS];
__device__ float g_bufA[ROWS * HID];
__device__ float g_bufB[ROWS * HID];
__device__ float g_pool[NGB * HID];             // per-block pool partials

// ---------------------------------------------------------------------------
// K1: one warp per adjacency row; 8 float4 loads up-front, warp-scan,
// uint16 ELL + dinv. 128MB read once -> HBM-bound.
// ---------------------------------------------------------------------------
__global__ void k_adj(const float4* __restrict__ adj4) {
    int gtid = blockIdx.x * blockDim.x + threadIdx.x;
    int row  = gtid >> 5;
    int lane = gtid & 31;
    if (row >= ROWS) return;

    const float4* rp = adj4 + (size_t)row * (NN / 4);
    float4 v[8];
    #pragma unroll
    for (int k = 0; k < 8; ++k) v[k] = rp[k * 32 + lane];

    int base = row * MAXN;
    int cnt = 0;
    #pragma unroll
    for (int k = 0; k < 8; ++k) {
        int col0 = (k * 32 + lane) * 4;
        int m = (v[k].x != 0.f ? 1 : 0) | (v[k].y != 0.f ? 2 : 0)
              | (v[k].z != 0.f ? 4 : 0) | (v[k].w != 0.f ? 8 : 0);
        int c = __popc(m);
        int x = c;
        #pragma unroll
        for (int d = 1; d < 32; d <<= 1) {
            int y = __shfl_up_sync(0xffffffffu, x, d);
            if (lane >= d) x += y;
        }
        int w   = cnt + x - c;
        int tot = __shfl_sync(0xffffffffu, x, 31);
        if (m & 1) { if (w < MAXN) g_nbr[base + w] = (unsigned short)col0;       w++; }
        if (m & 2) { if (w < MAXN) g_nbr[base + w] = (unsigned short)(col0 + 1); w++; }
        if (m & 4) { if (w < MAXN) g_nbr[base + w] = (unsigned short)(col0 + 2); w++; }
        if (m & 8) { if (w < MAXN) g_nbr[base + w] = (unsigned short)(col0 + 3); w++; }
        cnt += tot;
    }
    if (lane == 0) {
        g_cnt[row]  = cnt;
        g_dinv[row] = rsqrtf((float)(cnt > 0 ? cnt : 1));
    }
}

// ---------------------------------------------------------------------------
// K2: z0[row] = dinv[row] * (x[row] @ W1). 64 rows / 256-thread block.
// ---------------------------------------------------------------------------
__global__ void __launch_bounds__(256) k_lin0(const float* __restrict__ x,
                                              const float* __restrict__ W1,
                                              float* __restrict__ out) {
    int tid = threadIdx.x;
    int g   = tid >> 6;
    int t   = tid & 63;
    int R0  = blockIdx.x * 64;

    __shared__ float sx[64 * ND];
    __shared__ float sdinv[64];

    float wreg[ND];
    #pragma unroll
    for (int c = 0; c < ND; ++c) wreg[c] = W1[c * HID + t];

    for (int i = tid; i < 64 * ND; i += 256) sx[i] = x[(size_t)R0 * ND + i];
    if (tid < 64) sdinv[tid] = g_dinv[R0 + tid];
    __syncthreads();

    #pragma unroll 4
    for (int rr = 0; rr < 16; ++rr) {
        int r = g * 16 + rr;
        const float* xr = sx + r * ND;
        float a = 0.f;
        #pragma unroll
        for (int c = 0; c < ND; ++c) a = fmaf(xr[c], wreg[c], a);
        out[(size_t)(R0 + r) * HID + t] = a * sdinv[r];
    }
}

// ---------------------------------------------------------------------------
// K3a: gather kernel. 32 rows / 256-thread block (grid 1024, smem ~4.5KB ->
// high occupancy). Warp w handles rows w*4..w*4+3 interleaved; lane = channel
// pair; packed add.rn.f32x2.  h = relu(dinv*agg + b).
//   POOL=0: write h rows to global.
//   POOL=1: accumulate per-block pool partials.
// ---------------------------------------------------------------------------
template <int POOL>
__global__ void __launch_bounds__(256) k_gather(const float* __restrict__ zin,
                                                const float* __restrict__ bias,
                                                float* __restrict__ out) {
    int tid  = threadIdx.x;
    int w    = tid >> 5;
    int lane = tid & 31;
    int R0   = blockIdx.x * GRPB;
    int bbase = (R0 >> 10) << 10;                 // batch * N

    __shared__ unsigned short sidx[GRPB * MAXN];  // 4 KB
    __shared__ int   scnt[GRPB];
    __shared__ float sdinv[GRPB];
    __shared__ float2 spart[8][32];

    {   // stage ELL lists: 32*64 u16 = 4KB = 256 int4
        ((int4*)sidx)[tid] = ((const int4*)(g_nbr + (size_t)R0 * MAXN))[tid];
        if (tid < GRPB) {
            int c = g_cnt[R0 + tid];
            scnt[tid]  = c > MAXN ? MAXN : c;
            sdinv[tid] = g_dinv[R0 + tid];
        }
    }
    __syncthreads();

    const float2 bf = ((const float2*)bias)[lane];
    const ull* zb = (const ull*)zin + (size_t)bbase * (HID / 2) + lane;

    int r0 = w * 4;
    int cn[4];
    const unsigned short* ip[4];
    ull acc[4];
    #pragma unroll
    for (int i = 0; i < 4; ++i) {
        cn[i]  = scnt[r0 + i];
        ip[i]  = sidx + (r0 + i) * MAXN;
        acc[i] = 0ull;
    }
    int cmax = max(max(cn[0], cn[1]), max(cn[2], cn[3]));

    #pragma unroll 2
    for (int k = 0; k < cmax; ++k) {
        #pragma unroll
        for (int i = 0; i < 4; ++i) {
            if (k < cn[i]) {
                ull v = zb[ip[i][k] * (HID / 2)];
                ADD2(acc[i], acc[i], v);
            }
        }
    }

    float2 pacc = make_float2(0.f, 0.f);
    #pragma unroll
    for (int i = 0; i < 4; ++i) {
        float ax, ay;
        UNPACK2(ax, ay, acc[i]);
        float di = sdinv[r0 + i];
        float hx = fmaxf(fmaf(di, ax, bf.x), 0.f);
        float hy = fmaxf(fmaf(di, ay, bf.y), 0.f);
        if (!POOL) {
            *(float2*)(out + (size_t)(R0 + r0 + i) * HID + 2 * lane) = make_float2(hx, hy);
        } else {
            pacc.x += hx; pacc.y += hy;
        }
    }

    if (POOL) {
        spart[w][lane] = pacc;
        __syncthreads();
        if (tid < 32) {
            float2 s = spart[0][tid];
            #pragma unroll
            for (int i = 1; i < 8; ++i) { s.x += spart[i][tid].x; s.y += spart[i][tid].y; }
            *(float2*)(out + blockIdx.x * HID + 2 * tid) = s;
        }
    }
}

// ---------------------------------------------------------------------------
// K3b: matvec kernel. z' = dinv * (h @ W). 32 rows / 128-thread block
// (grid 1024, smem ~24.5KB -> ~7 blocks/SM). Thread tile 4 rows x 4 cols,
// packed FMA2 — the proven R5 phase-2 layout.
// ---------------------------------------------------------------------------
__global__ void __launch_bounds__(128) k_mv(const float* __restrict__ hin,
                                            const float* __restrict__ W,
                                            float* __restrict__ out) {
    int tid = threadIdx.x;
    int R0  = blockIdx.x * GRPB;

    __shared__ float sh[GRPB * MVPAD];   // 8.1 KB
    __shared__ float sW[HID * HID];      // 16 KB
    __shared__ float sdinv[GRPB];

    {   // stage W (4096 floats = 1024 float4, 8 per thread)
        const float4* ws = (const float4*)W;
        float4* wd = (float4*)sW;
        #pragma unroll
        for (int i = 0; i < 8; ++i) wd[tid + i * 128] = ws[tid + i * 128];
        // stage h (32*64 floats = 512 float4, 4 per thread) into padded smem
        const float4* hs = (const float4*)(hin + (size_t)R0 * HID);
        #pragma unroll
        for (int i = 0; i < 4; ++i) {
            int i4  = tid + i * 128;
            float4 v = hs[i4];
            int row = (i4 * 4) >> 6;
            int col = (i4 * 4) & 63;
            float* d = sh + row * MVPAD + col;
            d[0] = v.x; d[1] = v.y; d[2] = v.z; d[3] = v.w;
        }
        if (tid < GRPB) sdinv[tid] = g_dinv[R0 + tid];
    }
    __syncthreads();

    int tx = tid & 15;          // cols 4*tx .. 4*tx+3
    int ty = tid >> 4;          // rows 4*ty .. 4*ty+3

    ull acc[4][2];
    #pragma unroll
    for (int i = 0; i < 4; ++i) { acc[i][0] = 0ull; acc[i][1] = 0ull; }

    const float* shb = sh + (4 * ty) * MVPAD;
    #pragma unroll 4
    for (int c = 0; c < HID; ++c) {
        ulonglong2 wv = *(const ulonglong2*)(sW + c * HID + 4 * tx);
        #pragma unroll
        for (int i = 0; i < 4; ++i) {
            float hv = shb[i * MVPAD + c];
            ull hh; DUP2(hh, hv);
            FMA2(acc[i][0], hh, wv.x, acc[i][0]);
            FMA2(acc[i][1], hh, wv.y, acc[i][1]);
        }
    }

    #pragma unroll
    for (int i = 0; i < 4; ++i) {
        int r = 4 * ty + i;
        float di = sdinv[r];
        float a0, a1, a2, a3;
        UNPACK2(a0, a1, acc[i][0]);
        UNPACK2(a2, a3, acc[i][1]);
        float4 o;
        o.x = di * a0; o.y = di * a1; o.z = di * a2; o.w = di * a3;
        *(float4*)(out + (size_t)(R0 + r) * HID + 4 * tx) = o;
    }
}

// ---------------------------------------------------------------------------
// K4: per batch: pooled = mean of 32 block partials; relu(pooled@Wf1+bf1)@Wf2+bf2
// ---------------------------------------------------------------------------
__global__ void k_final(const float* __restrict__ pool,
                        const float* __restrict__ Wf1, const float* __restrict__ bf1,
                        const float* __restrict__ Wf2, const float* __restrict__ bf2,
                        float* __restrict__ out) {
    int b   = blockIdx.x;
    int tid = threadIdx.x;           // 128 threads
    __shared__ float pooled[HID];
    __shared__ float hred[HEADD];

    if (tid < HID) {
        float s = 0.f;
        #pragma unroll
        for (int i = 0; i < NN / GRPB; ++i)
            s += pool[(b * (NN / GRPB) + i) * HID + tid];
        pooled[tid] = s * (1.f / NN);
    }
    __syncthreads();

    float a = bf1[tid];
    #pragma unroll
    for (int c = 0; c < HID; ++c) a = fmaf(pooled[c], Wf1[c * HEADD + tid], a);
    hred[tid] = fmaxf(a, 0.f) * Wf2[tid];
    __syncthreads();

    if (tid < 32) {
        float s = hred[tid] + hred[tid + 32] + hred[tid + 64] + hred[tid + 96];
        #pragma unroll
        for (int d = 16; d; d >>= 1) s += __shfl_down_sync(0xffffffffu, s, d);
        if (tid == 0) out[b] = s + bf2[0];
    }
}

// ---------------------------------------------------------------------------
extern "C" void kernel_launch(void* const* d_in, const int* in_sizes, int n_in,
                              void* d_out, int out_size) {
    const float* x    = (const float*)d_in[0];
    const float* adj  = (const float*)d_in[1];
    const float* W1   = (const float*)d_in[2];
    const float* b1   = (const float*)d_in[3];
    const float* W2   = (const float*)d_in[4];
    const float* b2   = (const float*)d_in[5];
    const float* W3   = (const float*)d_in[6];
    const float* b3   = (const float*)d_in[7];
    const float* Wf1  = (const float*)d_in[8];
    const float* bf1  = (const float*)d_in[9];
    const float* Wf2  = (const float*)d_in[10];
    const float* bf2  = (const float*)d_in[11];
    float* out = (float*)d_out;

    float *bufA, *bufB, *pool;
    cudaGetSymbolAddress((void**)&bufA, g_bufA);
    cudaGetSymbolAddress((void**)&bufB, g_bufB);
    cudaGetSymbolAddress((void**)&pool, g_pool);

    k_adj<<<ROWS * 32 / 256, 256>>>((const float4*)adj);         // ELL + dinv
    k_lin0<<<ROWS / 64, 256>>>(x, W1, bufA);                     // z0 -> A
    k_gather<0><<<NGB, 256>>>(bufA, b1, bufB);                   // h1 -> B
    k_mv<<<NGB, 128>>>(bufB, W2, bufA);                          // z1 -> A
    k_gather<0><<<NGB, 256>>>(bufA, b2, bufB);                   // h2 -> B
    k_mv<<<NGB, 128>>>(bufB, W3, bufA);                          // z2 -> A
    k_gather<1><<<NGB, 256>>>(bufA, b3, pool);                   // pool partials
    k_final<<<BB, HEADD>>>(pool, Wf1, bf1, Wf2, bf2, out);       // head
}